// round 10
// baseline (speedup 1.0000x reference)
#include <cuda_runtime.h>
#include <cuda_bf16.h>

#define PP     76800     // H*W
#define HH     240
#define WW     320
#define NC     22        // classes
#define NR     6         // u64 per query row (24 u16 class lanes >= 22)
#define NQ     300       // query points (15*20)
#define QW     20
#define QSKIP  16
#define EPSF   1e-6f
#define C1F    (0.9f * 1e-6f)

#define THR    320       // one thread per pixel of the block's row
#define BLKS   240       // 1 image row per block; 4+ blocks/SM => co-resident

typedef unsigned long long ull;

// ---------------- device scratch (zero-init; reset by last block each launch) -
__device__ ull   g_accP[NQ * NR];
__device__ int   g_clsCnt[NC];
__device__ float g_zsum[NC];
__device__ int   g_phase1;
__device__ int   g_phase2;

// Exact inlier bit — byte-identical op sequence to rounds 4..9.
__device__ __forceinline__ unsigned ibit(float cx, float cy, float ux, float uy,
                                         float K) {
    float s   = cx * cx;
    float rhs = fmaf(s, 0.81f, K);
    float w   = fmaf(cy, uy, -C1F);
    float tv  = fmaf(cx, ux, w);
    float tt  = tv * fabsf(tv);
    float d   = fmaf(tt, -1.0f, rhs);
    return __float_as_uint(d) >> 31;
}

// =============== single persistent kernel ====================================
__global__ void __launch_bounds__(THR) k_all(const int* __restrict__ label,
                                             const float* __restrict__ vp,
                                             const float* __restrict__ extents,
                                             const float* __restrict__ poses,
                                             const float* __restrict__ mdata,
                                             float* __restrict__ out) {
    __shared__ union {
        unsigned int hist[NQ * NC];   // 26.4 KB vote histogram (u32 atomics)
        ull          tab[NQ * NR];    // 14.4 KB staged vote table
    } sB;
    __shared__ int   sCC[NC];
    __shared__ int   sBQ[NC];
    __shared__ float sBV[NC];
    __shared__ float sZ[NC];
    __shared__ int   sLast;

    int t    = threadIdx.x;
    int lane = t & 31;
    int row  = blockIdx.x;

    for (int i = t; i < NQ * NC; i += THR) sB.hist[i] = 0u;
    if (t < NC) { sCC[t] = 0; sZ[t] = 0.0f; }
    if (t == 0) sLast = 0;

    // ---------------- prep: this thread's pixel (stays in registers) ---------
    int p   = row * WW + t;
    int lab = label[p];
    float ux = 0.0f, uy = 0.0f, dz = 0.0f;
    if (lab > 0) {
        float dx = vp[(3 * lab + 0) * PP + p];
        float dy = vp[(3 * lab + 1) * PP + p];
        dz       = vp[(3 * lab + 2) * PP + p];
        float dn = sqrtf(dx * dx + dy * dy) + EPSF;
        ux = dx / dn;
        uy = dy / dn;
    }
    {
        unsigned m = __match_any_sync(0xffffffffu, lab);
        if (lane == __ffs(m) - 1) atomicAdd(&sCC[lab], __popc(m));
    }
    __syncthreads();

    // ---------------- vote: per query row, cone/line interval + exact tests --
    // Cone {c : (u.c)/(|c|+eps) > 0.9} is convex => per row, passing qx form a
    // single interval. Compute a conservative superset (slack +-2 px), then run
    // the EXACT ibit on candidates only -> vote counts identical to brute force.
    if (lab > 0) {
        float n2  = fmaf(ux, ux, uy * uy);                    // ~1
        float s   = 0.9f * sqrtf(fmaxf(n2 - 0.81f, 0.0f));
        float a   = fmaf(ux, ux, -0.81f);
        bool  fb  = fabsf(a) < 1e-5f;                         // degenerate: test all
        float inva = 1.0f / a;
        float m    = -ux * uy;
        float fpx  = (float)t;
        for (int r = 0; r < 15; r++) {
            float cy = (float)(r * QSKIP - row);              // exact small int
            float q1 = cy * (m + s) * inva;
            float q2 = cy * (m - s) * inva;
            float rlo = fminf(q1, q2), rhi = fmaxf(q1, q2);
            float L, H;
            if (a < 0.0f) {                                   // between roots
                L = rlo; H = rhi;
                float mid = 0.5f * (rlo + rhi);
                float dm  = fmaf(ux, mid, uy * cy);
                if (dm <= 0.0f) { L = 1e9f; H = -1e9f; }      // reflected cone
            } else {                                          // one ray
                if (ux > 0.0f) { L = rhi;  H = 1e9f; }
                else           { L = -1e9f; H = rlo; }
            }
            if (fb) { L = -1e9f; H = 1e9f; }
            float lo = fmaxf(fpx + L - 2.0f, -1e8f);
            float hi = fminf(fpx + H + 2.0f,  1e8f);
            int i0 = max(0,  (int)ceilf (lo * 0.0625f));
            int i1 = min(QW - 1, (int)floorf(hi * 0.0625f));
            float K = (0.81f * cy) * cy;
            for (int i = i0; i <= i1; i++) {
                float cx = (float)(i * QSKIP) - fpx;          // exact small int
                if (ibit(cx, cy, ux, uy, K))
                    atomicAdd(&sB.hist[(r * QW + i) * NC + lab], 1u);
            }
        }
    }
    __syncthreads();

    // ---------------- flush: pack 4 u16 lanes per u64, 6 REDs per query ------
    if (t < NQ) {
        const unsigned int* hq = &sB.hist[t * NC];
        #pragma unroll
        for (int g = 0; g < NR; g++) {
            int c0 = 4 * g;
            ull v = (ull)hq[c0];
            if (c0 + 1 < NC) v |= (ull)hq[c0 + 1] << 16;
            if (c0 + 2 < NC) v |= (ull)hq[c0 + 2] << 32;
            if (c0 + 3 < NC) v |= (ull)hq[c0 + 3] << 48;
            if (v) atomicAdd(&g_accP[t * NR + g], v);         // exact u16 lanes
        }
    }
    if (t < NC && sCC[t]) atomicAdd(&g_clsCnt[t], sCC[t]);

    // ---------------- grid barrier (240 blocks, 4+/SM => all co-resident) ----
    __threadfence();
    __syncthreads();
    if (t == 0) {
        atomicAdd(&g_phase1, 1);
        while (atomicAdd(&g_phase1, 0) < BLKS) __nanosleep(64);
    }
    __syncthreads();

    // ---------------- phase 2: stage table (overwrites histogram) ------------
    for (int i = t; i < NQ * NR; i += THR) sB.tab[i] = __ldcg(&g_accP[i]);
    __syncthreads();

    // per-class argmax on u16 lanes, integer compare (first-index ties)
    {
        int w = t >> 5;                          // 10 warps
        for (int c = w; c < NC; c += 10) {
            int g  = c >> 2;
            int sh = (c & 3) * 16;
            int best = -1, bq = 0;
            for (int q = lane; q < NQ; q += 32) {
                int v = (int)((sB.tab[q * NR + g] >> sh) & 0xFFFFu);
                if (v > best) { best = v; bq = q; }
            }
            #pragma unroll
            for (int off = 16; off; off >>= 1) {
                int ov = __shfl_down_sync(0xffffffffu, best, off);
                int oq = __shfl_down_sync(0xffffffffu, bq,   off);
                if (ov > best || (ov == best && oq < bq)) { best = ov; bq = oq; }
            }
            if (lane == 0) { sBQ[c] = bq; sBV[c] = (float)best; }
        }
    }
    __syncthreads();

    // z-sum: this thread's pixel (registers survived the barrier)
    if (lab > 0) {
        int q = sBQ[lab];
        float qx = (float)((q % QW) * QSKIP);
        float qy = (float)((q / QW) * QSKIP);
        float cy = qy - (float)row;
        float K  = (0.81f * cy) * cy;
        float cx = qx - (float)t;
        if (ibit(cx, cy, ux, uy, K))             // same rounding as vote
            atomicAdd(&sZ[lab], dz);
    }
    __syncthreads();
    if (t < NC && sZ[t] != 0.0f) atomicAdd(&g_zsum[t], sZ[t]);
    __threadfence();
    __syncthreads();
    if (t == 0) {
        if (atomicAdd(&g_phase2, 1) == BLKS - 1) sLast = 1;
    }
    __syncthreads();
    if (!sLast) return;

    // ================= last block: assemble output + reset scratch ===========
    if (t < NC) {
        int c = t;
        float fx  = mdata[0] + EPSF;
        float fy  = mdata[4] + EPSF;
        float ppx = mdata[2];
        float ppy = mdata[5];

        float bv = sBV[c];
        int   bq = sBQ[c];
        float bx = (float)((bq % QW) * QSKIP);
        float by = (float)((bq / QW) * QSKIP);

        float cc = (float)__ldcg(&g_clsCnt[c]);
        float z  = __ldcg(&g_zsum[c]) / (bv + EPSF);   // cnt == best_votes

        float ex = extents[c * 3 + 0];
        float ey = extents[c * 3 + 1];
        float ez = extents[c * 3 + 2];
        float half = 0.5f * sqrtf(ex * ex + ey * ey + ez * ez);

        float zsafe = (fabsf(z) > EPSF) ? z : EPSF;
        float r = fx * half / zsafe;

        bool valid = (bv >= 50.0f) && (cc >= 500.0f) && (bv / (cc + EPSF) >= 0.02f);
        float score = valid ? bv : 0.0f;

        float* o = out + c * 14;
        o[0]  = 0.0f;
        o[1]  = (float)c;
        o[2]  = bx - r;
        o[3]  = by - r;
        o[4]  = bx + r;
        o[5]  = by + r;
        o[6]  = score;
        o[7]  = poses[c * 13 + 6];
        o[8]  = poses[c * 13 + 7];
        o[9]  = poses[c * 13 + 8];
        o[10] = poses[c * 13 + 9];
        o[11] = (bx - ppx) * z / fx;
        o[12] = (by - ppy) * z / fy;
        o[13] = z;

        g_clsCnt[c] = 0;                 // reset for next graph replay
        g_zsum[c]   = 0.0f;
    }
    for (int i = t; i < NQ * NR; i += THR) g_accP[i] = 0ULL;
    __threadfence();
    if (t == 0) { g_phase1 = 0; g_phase2 = 0; }
}

// ---------------- launch ------------------------------------------------------
extern "C" void kernel_launch(void* const* d_in, const int* in_sizes, int n_in,
                              void* d_out, int out_size) {
    const int*   label   = (const int*)  d_in[0];   // (1,240,320) int32
    const float* vp      = (const float*)d_in[1];   // (1,66,240,320) f32
    const float* extents = (const float*)d_in[2];   // (22,3) f32
    const float* poses   = (const float*)d_in[3];   // (22,13) f32
    const float* mdata   = (const float*)d_in[4];   // (1,9) f32
    float*       out     = (float*)d_out;           // (1,22,14) f32

    k_all<<<BLKS, THR>>>(label, vp, extents, poses, mdata, out);
}

// round 11
// speedup vs baseline: 1.4795x; 1.4795x over previous
#include <cuda_runtime.h>
#include <cuda_bf16.h>

#define PP     76800     // H*W
#define HH     240
#define WW     320
#define NC     22        // classes
#define RW     24        // u16 lanes per hist row (48B)
#define NR     6         // u64 per hist row
#define NQ     300       // query points (15*20)
#define QW     20
#define QSKIP  16
#define EPSF   1e-6f
#define C1F    (0.9f * 1e-6f)

#define VTHR   640       // vote threads: 2 class-parity copies of 300 queries
#define VBLKS  240       // 1 image row per block
#define MAXPR  192       // max pixel pairs after per-class pad-to-4

typedef unsigned long long ull;

// ---------------- device scratch (zero-init; reset by k_final each launch) ---
__device__ ull   g_accP[NQ * NR];      // vote counts, 4 u16 lanes / u64
__device__ float g_zsumT[NQ * NC];     // z-sum per (query, class)
__device__ int   g_clsCnt[NC];

// ---------------- packed f32x2 ops --------------------------------------------
#define FMA2(d,a,b,c) asm("fma.rn.f32x2 %0,%1,%2,%3;" : "=l"(d) : "l"(a),"l"(b),"l"(c))
#define MUL2(d,a,b)   asm("mul.rn.f32x2 %0,%1,%2;"   : "=l"(d) : "l"(a),"l"(b))
#define ADD2(d,a,b)   asm("add.rn.f32x2 %0,%1,%2;"   : "=l"(d) : "l"(a),"l"(b))

__device__ __forceinline__ ull pk2(float x) {
    unsigned u = __float_as_uint(x);
    return (ull)u | ((ull)u << 32);
}

// Packed inlier test, 2 pixels/call. Per-lane RN op sequence identical to all
// prior passing rounds -> vote bits unchanged. Returns raw d2 (sign = inlier).
__device__ __forceinline__ ull ptest2(ull ux2, ull uy2, ull npx2, ull qx2,
                                      ull cy2, ull K2, ull mC1F2,
                                      ull c81_2, ull mOne2) {
    ull cx2, s2, rhs2, w2, t2, tt2, d2;
    ADD2(cx2, qx2, npx2);                        // cx = qx + (-px)
    MUL2(s2, cx2, cx2);
    FMA2(rhs2, s2, c81_2, K2);                   // rhs = cx^2*0.81 + K
    FMA2(w2, cy2, uy2, mC1F2);                   // w = cy*uy - C1F
    FMA2(t2, cx2, ux2, w2);                      // t = cx*ux + w
    ull ta2 = t2 & 0x7FFFFFFF7FFFFFFFULL;        // |t| per lane
    MUL2(tt2, t2, ta2);                          // tt = t*|t|
    FMA2(d2, tt2, mOne2, rhs2);                  // d = rhs - tt  (sign => vote)
    return d2;
}

// =============== kernel 1: prep + vote + z-table ==============================
__global__ void __launch_bounds__(VTHR, 2) k_vote(const int* __restrict__ label,
                                                  const float* __restrict__ vp) {
    __shared__ unsigned short sHist[NQ * RW];   // 14.4 KB (direct stores)
    __shared__ float          sZrow[NQ * NC];   // 26.4 KB (direct stores)
    __shared__ ulonglong2     sU[MAXPR];        // (ux0|ux1, uy0|uy1)      3 KB
    __shared__ ulonglong2     sN[MAXPR];        // (npx0|npx1, dz0|dz1)    3 KB
    __shared__ int sPst[NC + 1];                // padded class starts [1..22]
    __shared__ int sCur[NC];
    __shared__ int sCC[NC];

    int t    = threadIdx.x;
    int lane = t & 31;
    int row  = blockIdx.x;

    for (int i = t; i < NQ * RW / 2; i += VTHR)
        reinterpret_cast<unsigned int*>(sHist)[i] = 0u;
    for (int i = t; i < NQ * NC; i += VTHR) sZrow[i] = 0.0f;
    for (int i = t; i < MAXPR * 4; i += VTHR) {
        reinterpret_cast<unsigned int*>(sU)[i] = 0u;   // pads: never vote
        reinterpret_cast<unsigned int*>(sN)[i] = 0u;
    }
    if (t < NC) sCC[t] = 0;
    __syncthreads();

    // ---------------- prep: one pixel per thread (t < 320) -------------------
    float ux = 0.0f, uy = 0.0f, dz = 0.0f;
    int   lab = 0;
    if (t < WW) {
        int p = row * WW + t;
        lab = label[p];
        if (lab > 0) {
            float dx = vp[(3 * lab + 0) * PP + p];
            float dy = vp[(3 * lab + 1) * PP + p];
            dz       = vp[(3 * lab + 2) * PP + p];
            float dn = sqrtf(dx * dx + dy * dy) + EPSF;
            ux = dx / dn;
            uy = dy / dn;
        }
        unsigned m = __match_any_sync(0xffffffffu, lab);
        if (lane == __ffs(m) - 1) atomicAdd(&sCC[lab], __popc(m));
    }
    __syncthreads();

    // padded segment starts (warp 0): class c = lane+1, count padded to x4
    if (t < 32) {
        int c = t + 1;
        int v = (t < 21) ? ((sCC[c] + 3) & ~3) : 0;
        int s = v;
        #pragma unroll
        for (int o = 1; o < 32; o <<= 1) {
            int u = __shfl_up_sync(0xffffffffu, s, o);
            if (lane >= o) s += u;
        }
        if (t < 21) {
            int excl = s - v;
            sPst[c]  = excl;
            sCur[c]  = excl;
            if (t == 20) sPst[22] = s;
        }
    }
    __syncthreads();

    // scatter fg pixels into padded, class-sorted packed arrays
    if (t < WW && lab > 0) {
        int pos  = atomicAdd(&sCur[lab], 1);
        int pair = pos >> 1, sub = pos & 1;
        float* uP = reinterpret_cast<float*>(sU);
        uP[pair * 4 + sub]     = ux;
        uP[pair * 4 + 2 + sub] = uy;
        float* nP = reinterpret_cast<float*>(sN);
        nP[pair * 4 + sub]     = -(float)t;
        nP[pair * 4 + 2 + sub] = dz;
    }
    __syncthreads();

    // ---------------- vote: packed test + fused z accumulation ---------------
    {
        int c0 = 0, tq = -1;
        if (t < NQ)                   { tq = t;       c0 = 1; }   // odd classes
        else if (t >= 320 && t < 620) { tq = t - 320; c0 = 2; }   // even classes
        if (tq >= 0) {
            float qx = (float)((tq % QW) * QSKIP);
            float qy = (float)((tq / QW) * QSKIP);
            float cy = qy - (float)row;
            float K  = (0.81f * cy) * cy;
            ull qx2   = pk2(qx);
            ull cy2   = pk2(cy);
            ull K2    = pk2(K);
            ull mC1F2 = pk2(-C1F);
            ull c81_2 = pk2(0.81f);
            ull mOne2 = pk2(-1.0f);
            for (int c = c0; c < NC; c += 2) {
                int pb = sPst[c] >> 1;
                int pe = sPst[c + 1] >> 1;           // multiple of 2 pairs
                unsigned cnt = 0;
                float zacc = 0.0f;
                for (int i = pb; i < pe; i += 2) {
                    ulonglong2 ua = sU[i];
                    ulonglong2 na = sN[i];
                    ulonglong2 ub = sU[i + 1];
                    ulonglong2 nb = sN[i + 1];
                    ull da = ptest2(ua.x, ua.y, na.x, qx2, cy2, K2, mC1F2, c81_2, mOne2);
                    ull db = ptest2(ub.x, ub.y, nb.x, qx2, cy2, K2, mC1F2, c81_2, mOne2);
                    unsigned a0 = (unsigned)(da >> 31) & 1u, a1 = (unsigned)(da >> 63);
                    unsigned b0 = (unsigned)(db >> 31) & 1u, b1 = (unsigned)(db >> 63);
                    cnt += a0 + a1 + b0 + b1;
                    zacc += a0 ? __uint_as_float((unsigned)na.y)         : 0.0f;
                    zacc += a1 ? __uint_as_float((unsigned)(na.y >> 32)) : 0.0f;
                    zacc += b0 ? __uint_as_float((unsigned)nb.y)         : 0.0f;
                    zacc += b1 ? __uint_as_float((unsigned)(nb.y >> 32)) : 0.0f;
                }
                sHist[tq * RW + c] = (unsigned short)cnt;   // disjoint lanes
                sZrow[tq * NC + c] = zacc;                  // disjoint slots
            }
        }
    }
    __syncthreads();

    // ---------------- flush: counts (6 u64 REDs) + nonzero z REDs ------------
    if (t < NQ) {
        const ull* r = reinterpret_cast<const ull*>(&sHist[t * RW]);
        #pragma unroll
        for (int k = 0; k < NR; k++) {
            ull v = r[k];
            if (v) atomicAdd(&g_accP[t * NR + k], v);       // exact u16 lanes
        }
        #pragma unroll
        for (int c = 1; c < NC; c++) {
            float z = sZrow[t * NC + c];
            if (z != 0.0f) atomicAdd(&g_zsumT[t * NC + c], z);
        }
    }
    if (t < NC && sCC[t]) atomicAdd(&g_clsCnt[t], sCC[t]);
}

// =============== kernel 2: single-block argmax + final + reset ===============
__global__ void __launch_bounds__(VTHR) k_final(const float* __restrict__ extents,
                                                const float* __restrict__ poses,
                                                const float* __restrict__ mdata,
                                                float* __restrict__ out) {
    __shared__ ull   sT[NQ * NR];    // 14.4 KB staged vote table
    __shared__ int   sBQ[NC];
    __shared__ float sBV[NC];

    int t    = threadIdx.x;
    int lane = t & 31;

    for (int i = t; i < NQ * NR; i += VTHR) sT[i] = g_accP[i];
    __syncthreads();

    // per-class argmax on u16 lanes (first-index ties)
    {
        int w = t >> 5;                          // 20 warps
        for (int c = w; c < NC; c += 20) {
            int g  = c >> 2;
            int sh = (c & 3) * 16;
            int best = -1, bq = 0;
            for (int q = lane; q < NQ; q += 32) {
                int v = (int)((sT[q * NR + g] >> sh) & 0xFFFFu);
                if (v > best) { best = v; bq = q; }
            }
            #pragma unroll
            for (int off = 16; off; off >>= 1) {
                int ov = __shfl_down_sync(0xffffffffu, best, off);
                int oq = __shfl_down_sync(0xffffffffu, bq,   off);
                if (ov > best || (ov == best && oq < bq)) { best = ov; bq = oq; }
            }
            if (lane == 0) { sBQ[c] = bq; sBV[c] = (float)best; }
        }
    }
    __syncthreads();

    if (t < NC) {
        int c = t;
        float fx  = mdata[0] + EPSF;
        float fy  = mdata[4] + EPSF;
        float ppx = mdata[2];
        float ppy = mdata[5];

        float bv = sBV[c];
        int   bq = sBQ[c];
        float bx = (float)((bq % QW) * QSKIP);
        float by = (float)((bq / QW) * QSKIP);

        float cc = (float)g_clsCnt[c];
        float z  = g_zsumT[bq * NC + c] / (bv + EPSF);  // cnt == best_votes

        float ex = extents[c * 3 + 0];
        float ey = extents[c * 3 + 1];
        float ez = extents[c * 3 + 2];
        float half = 0.5f * sqrtf(ex * ex + ey * ey + ez * ez);

        float zsafe = (fabsf(z) > EPSF) ? z : EPSF;
        float r = fx * half / zsafe;

        bool valid = (bv >= 50.0f) && (cc >= 500.0f) && (bv / (cc + EPSF) >= 0.02f);
        float score = valid ? bv : 0.0f;

        float* o = out + c * 14;
        o[0]  = 0.0f;
        o[1]  = (float)c;
        o[2]  = bx - r;
        o[3]  = by - r;
        o[4]  = bx + r;
        o[5]  = by + r;
        o[6]  = score;
        o[7]  = poses[c * 13 + 6];
        o[8]  = poses[c * 13 + 7];
        o[9]  = poses[c * 13 + 8];
        o[10] = poses[c * 13 + 9];
        o[11] = (bx - ppx) * z / fx;
        o[12] = (by - ppy) * z / fy;
        o[13] = z;

        g_clsCnt[c] = 0;                 // reset for next graph replay
    }
    __syncthreads();
    for (int i = t; i < NQ * NR; i += VTHR) g_accP[i] = 0ULL;
    for (int i = t; i < NQ * NC; i += VTHR) g_zsumT[i] = 0.0f;
}

// ---------------- launch ------------------------------------------------------
extern "C" void kernel_launch(void* const* d_in, const int* in_sizes, int n_in,
                              void* d_out, int out_size) {
    const int*   label   = (const int*)  d_in[0];   // (1,240,320) int32
    const float* vp      = (const float*)d_in[1];   // (1,66,240,320) f32
    const float* extents = (const float*)d_in[2];   // (22,3) f32
    const float* poses   = (const float*)d_in[3];   // (22,13) f32
    const float* mdata   = (const float*)d_in[4];   // (1,9) f32
    float*       out     = (float*)d_out;           // (1,22,14) f32

    k_vote <<<VBLKS, VTHR>>>(label, vp);
    k_final<<<1, VTHR>>>(extents, poses, mdata, out);
}

// round 12
// speedup vs baseline: 1.5964x; 1.0790x over previous
#include <cuda_runtime.h>
#include <cuda_bf16.h>

#define PP     76800     // H*W
#define HH     240
#define WW     320
#define NC     22        // classes
#define NR     6         // u64 groups of 4 u16 class lanes
#define NQ     300       // query points (15*20)
#define QW     20
#define QH     15
#define QSKIP  16
#define EPSF   1e-6f
#define C1F    (0.9f * 1e-6f)

#define THR    320       // one thread per pixel of the block's row
#define BLKS   240       // 1 image row per block (co-residency proven in R10)

typedef unsigned long long ull;

// ---------------- device scratch (zero-init; reset by last block each launch) -
__device__ ull   g_accP[NQ * NR];
__device__ int   g_clsCnt[NC];
__device__ float g_zsum[NC];
__device__ int   g_phase1;
__device__ int   g_phase2;

// Exact inlier bit — byte-identical op sequence to rounds 4..11.
__device__ __forceinline__ unsigned ibit(float cx, float cy, float ux, float uy,
                                         float K) {
    float s   = cx * cx;
    float rhs = fmaf(s, 0.81f, K);
    float w   = fmaf(cy, uy, -C1F);
    float tv  = fmaf(cx, ux, w);
    float tt  = tv * fabsf(tv);
    float d   = fmaf(tt, -1.0f, rhs);
    return __float_as_uint(d) >> 31;
}

// =============== single persistent kernel ====================================
__global__ void __launch_bounds__(THR) k_all(const int* __restrict__ label,
                                             const float* __restrict__ vp,
                                             const float* __restrict__ extents,
                                             const float* __restrict__ poses,
                                             const float* __restrict__ mdata,
                                             float* __restrict__ out) {
    __shared__ union {
        unsigned int hist[NQ * NC];   // 26.4 KB vote histogram (u32 atomics)
        ull          tab[NQ * NR];    // 14.4 KB staged vote table
    } sB;
    __shared__ int   sCC[NC];
    __shared__ int   sBQ[NC];
    __shared__ float sBV[NC];
    __shared__ float sZ[NC];
    __shared__ int   sLast;

    int t    = threadIdx.x;
    int lane = t & 31;
    int row  = blockIdx.x;

    for (int i = t; i < NQ * NC; i += THR) sB.hist[i] = 0u;
    if (t < NC) { sCC[t] = 0; sZ[t] = 0.0f; }
    if (t == 0) sLast = 0;

    // ---------------- prep: this thread's pixel (stays in registers) ---------
    int p   = row * WW + t;
    int lab = label[p];
    float ux = 0.0f, uy = 0.0f, dz = 0.0f;
    if (lab > 0) {
        float dx = vp[(3 * lab + 0) * PP + p];
        float dy = vp[(3 * lab + 1) * PP + p];
        dz       = vp[(3 * lab + 2) * PP + p];
        float dn = sqrtf(dx * dx + dy * dy) + EPSF;
        ux = dx / dn;
        uy = dy / dn;
    }
    {
        unsigned m = __match_any_sync(0xffffffffu, lab);
        if (lane == __ffs(m) - 1) atomicAdd(&sCC[lab], __popc(m));
    }

    // class-membership mask for this lane's owned class (= lane id, 1..21)
    unsigned mymask = 0;
    #pragma unroll
    for (int c = 1; c < NC; c++) {
        unsigned m = __ballot_sync(0xffffffffu, lab == c);
        if (lane == c) mymask = m;
    }
    __syncthreads();

    // ---------------- vote: pixel-major SIMT + ballot + lane-class popc ------
    // Each lane tests ITS register pixel against the warp-uniform query; ballot
    // packs 32 bits; lane c accumulates class c. FP sequence == ibit (exact).
    {
        float fpx = (float)t;
        unsigned int* __restrict__ h = sB.hist;
        for (int r = 0; r < QH; r++) {
            float cy = (float)(r * QSKIP) - (float)row;   // exact small ints
            float K  = (0.81f * cy) * cy;
            float w  = fmaf(cy, uy, -C1F);
            float cx = -fpx;                              // qx = 0
            int qbase = r * QW * NC + lane;
            #pragma unroll 4
            for (int i = 0; i < QW; i++) {
                float s   = cx * cx;
                float rhs = fmaf(s, 0.81f, K);
                float tv  = fmaf(cx, ux, w);
                float tt  = tv * fabsf(tv);
                float d   = fmaf(tt, -1.0f, rhs);
                unsigned bits = __ballot_sync(0xffffffffu,
                                              (int)__float_as_uint(d) < 0);
                unsigned v = __popc(bits & mymask);
                if (v) atomicAdd(&h[qbase + i * NC], v);
                cx += 16.0f;                              // exact small ints
            }
        }
    }
    __syncthreads();

    // ---------------- flush: pack 4 u16 lanes per u64, 6 REDs per query ------
    if (t < NQ) {
        const unsigned int* hq = &sB.hist[t * NC];
        #pragma unroll
        for (int g = 0; g < NR; g++) {
            int c0 = 4 * g;
            ull v = (ull)hq[c0];
            if (c0 + 1 < NC) v |= (ull)hq[c0 + 1] << 16;
            if (c0 + 2 < NC) v |= (ull)hq[c0 + 2] << 32;
            if (c0 + 3 < NC) v |= (ull)hq[c0 + 3] << 48;
            if (v) atomicAdd(&g_accP[t * NR + g], v);     // exact u16 lanes
        }
    }
    if (t < NC && sCC[t]) atomicAdd(&g_clsCnt[t], sCC[t]);

    // ---------------- grid barrier (proven co-resident config) ---------------
    __threadfence();
    __syncthreads();
    if (t == 0) {
        atomicAdd(&g_phase1, 1);
        while (atomicAdd(&g_phase1, 0) < BLKS) __nanosleep(64);
    }
    __syncthreads();

    // ---------------- phase 2: stage table (overwrites histogram) ------------
    for (int i = t; i < NQ * NR; i += THR) sB.tab[i] = __ldcg(&g_accP[i]);
    __syncthreads();

    // per-class argmax on u16 lanes, integer compare (first-index ties)
    {
        int w = t >> 5;                          // 10 warps
        for (int c = w; c < NC; c += 10) {
            int g  = c >> 2;
            int sh = (c & 3) * 16;
            int best = -1, bq = 0;
            for (int q = lane; q < NQ; q += 32) {
                int v = (int)((sB.tab[q * NR + g] >> sh) & 0xFFFFu);
                if (v > best) { best = v; bq = q; }
            }
            #pragma unroll
            for (int off = 16; off; off >>= 1) {
                int ov = __shfl_down_sync(0xffffffffu, best, off);
                int oq = __shfl_down_sync(0xffffffffu, bq,   off);
                if (ov > best || (ov == best && oq < bq)) { best = ov; bq = oq; }
            }
            if (lane == 0) { sBQ[c] = bq; sBV[c] = (float)best; }
        }
    }
    __syncthreads();

    // z-sum: this thread's pixel (registers survived the barrier)
    if (lab > 0) {
        int q = sBQ[lab];
        float qx = (float)((q % QW) * QSKIP);
        float qy = (float)((q / QW) * QSKIP);
        float cy = qy - (float)row;
        float K  = (0.81f * cy) * cy;
        float cx = qx - (float)t;
        if (ibit(cx, cy, ux, uy, K))             // same rounding as vote
            atomicAdd(&sZ[lab], dz);
    }
    __syncthreads();
    if (t < NC && sZ[t] != 0.0f) atomicAdd(&g_zsum[t], sZ[t]);
    __threadfence();
    __syncthreads();
    if (t == 0) {
        if (atomicAdd(&g_phase2, 1) == BLKS - 1) sLast = 1;
    }
    __syncthreads();
    if (!sLast) return;

    // ================= last block: assemble output + reset scratch ===========
    if (t < NC) {
        int c = t;
        float fx  = mdata[0] + EPSF;
        float fy  = mdata[4] + EPSF;
        float ppx = mdata[2];
        float ppy = mdata[5];

        float bv = sBV[c];
        int   bq = sBQ[c];
        float bx = (float)((bq % QW) * QSKIP);
        float by = (float)((bq / QW) * QSKIP);

        float cc = (float)__ldcg(&g_clsCnt[c]);
        float z  = __ldcg(&g_zsum[c]) / (bv + EPSF);   // cnt == best_votes

        float ex = extents[c * 3 + 0];
        float ey = extents[c * 3 + 1];
        float ez = extents[c * 3 + 2];
        float half = 0.5f * sqrtf(ex * ex + ey * ey + ez * ez);

        float zsafe = (fabsf(z) > EPSF) ? z : EPSF;
        float r = fx * half / zsafe;

        bool valid = (bv >= 50.0f) && (cc >= 500.0f) && (bv / (cc + EPSF) >= 0.02f);
        float score = valid ? bv : 0.0f;

        float* o = out + c * 14;
        o[0]  = 0.0f;
        o[1]  = (float)c;
        o[2]  = bx - r;
        o[3]  = by - r;
        o[4]  = bx + r;
        o[5]  = by + r;
        o[6]  = score;
        o[7]  = poses[c * 13 + 6];
        o[8]  = poses[c * 13 + 7];
        o[9]  = poses[c * 13 + 8];
        o[10] = poses[c * 13 + 9];
        o[11] = (bx - ppx) * z / fx;
        o[12] = (by - ppy) * z / fy;
        o[13] = z;

        g_clsCnt[c] = 0;                 // reset for next graph replay
        g_zsum[c]   = 0.0f;
    }
    for (int i = t; i < NQ * NR; i += THR) g_accP[i] = 0ULL;
    __threadfence();
    if (t == 0) { g_phase1 = 0; g_phase2 = 0; }
}

// ---------------- launch ------------------------------------------------------
extern "C" void kernel_launch(void* const* d_in, const int* in_sizes, int n_in,
                              void* d_out, int out_size) {
    const int*   label   = (const int*)  d_in[0];   // (1,240,320) int32
    const float* vp      = (const float*)d_in[1];   // (1,66,240,320) f32
    const float* extents = (const float*)d_in[2];   // (22,3) f32
    const float* poses   = (const float*)d_in[3];   // (22,13) f32
    const float* mdata   = (const float*)d_in[4];   // (1,9) f32
    float*       out     = (float*)d_out;           // (1,22,14) f32

    k_all<<<BLKS, THR>>>(label, vp, extents, poses, mdata, out);
}

// round 13
// speedup vs baseline: 1.9433x; 1.2173x over previous
#include <cuda_runtime.h>
#include <cuda_bf16.h>

#define PP     76800     // H*W
#define HH     240
#define WW     320
#define NC     22        // classes
#define NR     6         // u64 groups of 4 u16 class lanes
#define NQ     300       // query points (15*20)
#define QW     20
#define QH     15
#define QSKIP  16
#define EPSF   1e-6f
#define C1F    (0.9f * 1e-6f)

#define THR    320       // one thread per pixel of the block's row
#define NW     10        // warps per block
#define BLKS   240       // 1 image row per block (co-residency proven R10/R12)

typedef unsigned long long ull;

// ---------------- device scratch (zero-init; reset by last block each launch) -
__device__ ull   g_accP[NQ * NR];
__device__ int   g_clsCnt[NC];
__device__ float g_zsum[NC];
__device__ int   g_phase1;
__device__ int   g_phase2;

// Exact inlier bit — byte-identical op sequence to rounds 4..12.
__device__ __forceinline__ unsigned ibit(float cx, float cy, float ux, float uy,
                                         float K) {
    float s   = cx * cx;
    float rhs = fmaf(s, 0.81f, K);
    float w   = fmaf(cy, uy, -C1F);
    float tv  = fmaf(cx, ux, w);
    float tt  = tv * fabsf(tv);
    float d   = fmaf(tt, -1.0f, rhs);
    return __float_as_uint(d) >> 31;
}

// =============== single persistent kernel ====================================
__global__ void __launch_bounds__(THR) k_all(const int* __restrict__ label,
                                             const float* __restrict__ vp,
                                             const float* __restrict__ extents,
                                             const float* __restrict__ poses,
                                             const float* __restrict__ mdata,
                                             float* __restrict__ out) {
    __shared__ union {
        unsigned int masks[NQ * NW];  // 12 KB raw inlier ballots [q][warp]
        ull          tab[NQ * NR];    // 14.4 KB staged vote table (phase 2)
    } sB;
    __shared__ unsigned int sClsm[NW * NC];   // per-warp class membership masks
    __shared__ int   sCC[NC];
    __shared__ int   sBQ[NC];
    __shared__ float sBV[NC];
    __shared__ float sZ[NC];
    __shared__ int   sLast;

    int t    = threadIdx.x;
    int lane = t & 31;
    int wid  = t >> 5;
    int row  = blockIdx.x;

    if (t < NC) { sCC[t] = 0; sZ[t] = 0.0f; }
    if (t == 0) sLast = 0;

    // ---------------- prep: this thread's pixel (stays in registers) ---------
    int p   = row * WW + t;
    int lab = label[p];
    float ux = 0.0f, uy = 0.0f, dz = 0.0f;
    if (lab > 0) {
        float dx = vp[(3 * lab + 0) * PP + p];
        float dy = vp[(3 * lab + 1) * PP + p];
        dz       = vp[(3 * lab + 2) * PP + p];
        float dn = sqrtf(dx * dx + dy * dy) + EPSF;
        ux = dx / dn;
        uy = dy / dn;
    }
    {
        unsigned m = __match_any_sync(0xffffffffu, lab);
        if (lane == __ffs(m) - 1) atomicAdd(&sCC[lab], __popc(m));
    }
    // per-warp class membership masks (bg class 0 => mask unused, store anyway)
    #pragma unroll
    for (int c = 0; c < NC; c++) {
        unsigned m = __ballot_sync(0xffffffffu, lab == c);
        if (lane == c) sClsm[wid * NC + c] = m;   // lanes 0..21 write
    }
    __syncthreads();

    // ---------------- vote: ballot per (warp, query), store raw mask ---------
    // Lane = pixel (registers). FP sequence == ibit exactly -> identical votes.
    {
        float fpx = (float)t;
        unsigned int* __restrict__ mk = sB.masks;
        int qa = wid;                                 // &masks[q*NW + wid]
        for (int r = 0; r < QH; r++) {
            float cy = (float)(r * QSKIP) - (float)row;   // exact small ints
            float K  = (0.81f * cy) * cy;
            float w  = fmaf(cy, uy, -C1F);
            float cx = -fpx;                              // qx = 0
            #pragma unroll 5
            for (int i = 0; i < QW; i++) {
                float s   = cx * cx;
                float rhs = fmaf(s, 0.81f, K);
                float tv  = fmaf(cx, ux, w);
                float tt  = tv * fabsf(tv);
                float d   = fmaf(tt, -1.0f, rhs);
                unsigned bits = __ballot_sync(0xffffffffu,
                                              (int)__float_as_uint(d) < 0);
                if (lane == 0) mk[qa] = bits;             // single STS.32
                qa += NW;
                cx += 16.0f;                              // exact small ints
            }
        }
    }
    __syncthreads();

    // ---------------- merge: per-query popc against class masks --------------
    if (t < NQ) {
        unsigned cnt[NC];
        #pragma unroll
        for (int c = 0; c < NC; c++) cnt[c] = 0;
        #pragma unroll
        for (int w = 0; w < NW; w++) {
            unsigned m = sB.masks[t * NW + w];            // 2-way conflict max
            if (m) {
                const unsigned* cm = &sClsm[w * NC];      // broadcast LDS
                #pragma unroll
                for (int c = 1; c < NC; c++)
                    cnt[c] += __popc(m & cm[c]);
            }
        }
        // pack 4 u16 lanes per u64, 6 REDs per query (exact integer sums)
        #pragma unroll
        for (int g = 0; g < NR; g++) {
            int c0 = 4 * g;
            ull v = (ull)cnt[c0];
            if (c0 + 1 < NC) v |= (ull)cnt[c0 + 1] << 16;
            if (c0 + 2 < NC) v |= (ull)cnt[c0 + 2] << 32;
            if (c0 + 3 < NC) v |= (ull)cnt[c0 + 3] << 48;
            if (v) atomicAdd(&g_accP[t * NR + g], v);
        }
    }
    if (t < NC && sCC[t]) atomicAdd(&g_clsCnt[t], sCC[t]);

    // ---------------- grid barrier (proven co-resident config) ---------------
    __threadfence();
    __syncthreads();
    if (t == 0) {
        atomicAdd(&g_phase1, 1);
        while (atomicAdd(&g_phase1, 0) < BLKS) __nanosleep(64);
    }
    __syncthreads();

    // ---------------- phase 2: stage table (overwrites masks) ----------------
    for (int i = t; i < NQ * NR; i += THR) sB.tab[i] = __ldcg(&g_accP[i]);
    __syncthreads();

    // per-class argmax on u16 lanes, integer compare (first-index ties)
    {
        int w = t >> 5;                          // 10 warps
        for (int c = w; c < NC; c += NW) {
            int g  = c >> 2;
            int sh = (c & 3) * 16;
            int best = -1, bq = 0;
            for (int q = lane; q < NQ; q += 32) {
                int v = (int)((sB.tab[q * NR + g] >> sh) & 0xFFFFu);
                if (v > best) { best = v; bq = q; }
            }
            #pragma unroll
            for (int off = 16; off; off >>= 1) {
                int ov = __shfl_down_sync(0xffffffffu, best, off);
                int oq = __shfl_down_sync(0xffffffffu, bq,   off);
                if (ov > best || (ov == best && oq < bq)) { best = ov; bq = oq; }
            }
            if (lane == 0) { sBQ[c] = bq; sBV[c] = (float)best; }
        }
    }
    __syncthreads();

    // z-sum: this thread's pixel (registers survived the barrier)
    if (lab > 0) {
        int q = sBQ[lab];
        float qx = (float)((q % QW) * QSKIP);
        float qy = (float)((q / QW) * QSKIP);
        float cy = qy - (float)row;
        float K  = (0.81f * cy) * cy;
        float cx = qx - (float)t;
        if (ibit(cx, cy, ux, uy, K))             // same rounding as vote
            atomicAdd(&sZ[lab], dz);
    }
    __syncthreads();
    if (t < NC && sZ[t] != 0.0f) atomicAdd(&g_zsum[t], sZ[t]);
    __threadfence();
    __syncthreads();
    if (t == 0) {
        if (atomicAdd(&g_phase2, 1) == BLKS - 1) sLast = 1;
    }
    __syncthreads();
    if (!sLast) return;

    // ================= last block: assemble output + reset scratch ===========
    if (t < NC) {
        int c = t;
        float fx  = mdata[0] + EPSF;
        float fy  = mdata[4] + EPSF;
        float ppx = mdata[2];
        float ppy = mdata[5];

        float bv = sBV[c];
        int   bq = sBQ[c];
        float bx = (float)((bq % QW) * QSKIP);
        float by = (float)((bq / QW) * QSKIP);

        float cc = (float)__ldcg(&g_clsCnt[c]);
        float z  = __ldcg(&g_zsum[c]) / (bv + EPSF);   // cnt == best_votes

        float ex = extents[c * 3 + 0];
        float ey = extents[c * 3 + 1];
        float ez = extents[c * 3 + 2];
        float half = 0.5f * sqrtf(ex * ex + ey * ey + ez * ez);

        float zsafe = (fabsf(z) > EPSF) ? z : EPSF;
        float r = fx * half / zsafe;

        bool valid = (bv >= 50.0f) && (cc >= 500.0f) && (bv / (cc + EPSF) >= 0.02f);
        float score = valid ? bv : 0.0f;

        float* o = out + c * 14;
        o[0]  = 0.0f;
        o[1]  = (float)c;
        o[2]  = bx - r;
        o[3]  = by - r;
        o[4]  = bx + r;
        o[5]  = by + r;
        o[6]  = score;
        o[7]  = poses[c * 13 + 6];
        o[8]  = poses[c * 13 + 7];
        o[9]  = poses[c * 13 + 8];
        o[10] = poses[c * 13 + 9];
        o[11] = (bx - ppx) * z / fx;
        o[12] = (by - ppy) * z / fy;
        o[13] = z;

        g_clsCnt[c] = 0;                 // reset for next graph replay
        g_zsum[c]   = 0.0f;
    }
    for (int i = t; i < NQ * NR; i += THR) g_accP[i] = 0ULL;
    __threadfence();
    if (t == 0) { g_phase1 = 0; g_phase2 = 0; }
}

// ---------------- launch ------------------------------------------------------
extern "C" void kernel_launch(void* const* d_in, const int* in_sizes, int n_in,
                              void* d_out, int out_size) {
    const int*   label   = (const int*)  d_in[0];   // (1,240,320) int32
    const float* vp      = (const float*)d_in[1];   // (1,66,240,320) f32
    const float* extents = (const float*)d_in[2];   // (22,3) f32
    const float* poses   = (const float*)d_in[3];   // (22,13) f32
    const float* mdata   = (const float*)d_in[4];   // (1,9) f32
    float*       out     = (float*)d_out;           // (1,22,14) f32

    k_all<<<BLKS, THR>>>(label, vp, extents, poses, mdata, out);
}

// round 14
// speedup vs baseline: 1.9451x; 1.0010x over previous
#include <cuda_runtime.h>
#include <cuda_bf16.h>

#define PP     76800     // H*W
#define HH     240
#define WW     320
#define NC     22        // classes
#define NR     6         // u64 groups of 4 u16 class lanes
#define NQ     300       // query points (15*20)
#define QW     20
#define QH     15
#define QSKIP  16
#define EPSF   1e-6f
#define C1F    (0.9f * 1e-6f)

#define THR    640       // 2 copies of the row's 320 pixels
#define NW     10        // mask slots per query (pixel warps per copy)
#define BLKS   240       // 1 image row per block; 2 blocks/SM => co-resident

typedef unsigned long long ull;

// ---------------- device scratch (zero-init; reset by last block each launch) -
__device__ ull   g_accP[NQ * NR];
__device__ int   g_clsCnt[NC];
__device__ float g_zsum[NC];
__device__ int   g_phase1;
__device__ int   g_phase2;

// Exact inlier bit — byte-identical op sequence to rounds 4..13.
__device__ __forceinline__ unsigned ibit(float cx, float cy, float ux, float uy,
                                         float K) {
    float s   = cx * cx;
    float rhs = fmaf(s, 0.81f, K);
    float w   = fmaf(cy, uy, -C1F);
    float tv  = fmaf(cx, ux, w);
    float tt  = tv * fabsf(tv);
    float d   = fmaf(tt, -1.0f, rhs);
    return __float_as_uint(d) >> 31;
}

// =============== single persistent kernel ====================================
__global__ void __launch_bounds__(THR) k_all(const int* __restrict__ label,
                                             const float* __restrict__ vp,
                                             const float* __restrict__ extents,
                                             const float* __restrict__ poses,
                                             const float* __restrict__ mdata,
                                             float* __restrict__ out) {
    __shared__ union {
        unsigned int masks[NQ * NW];  // 12 KB raw inlier ballots [q][warpslot]
        ull          tab[NQ * NR];    // 14.4 KB staged vote table (phase 2)
    } sB;
    __shared__ unsigned int sClsm[NW * NC];   // per-pixel-warp class masks
    __shared__ int   sCC[NC];
    __shared__ int   sBQ[NC];
    __shared__ float sBV[NC];
    __shared__ float sZ[NC];
    __shared__ int   sLast;

    int t    = threadIdx.x;
    int lane = t & 31;
    int wid  = t >> 5;
    int row  = blockIdx.x;

    if (t < NC) { sCC[t] = 0; sZ[t] = 0.0f; }
    if (t == 0) sLast = 0;

    // ---------------- prep: pixel in registers (copies share pixels) ---------
    int px  = (t < WW) ? t : (t - WW);          // pixel column
    int p   = row * WW + px;
    int lab = label[p];
    float ux = 0.0f, uy = 0.0f, dz = 0.0f;
    if (lab > 0) {
        float dx = vp[(3 * lab + 0) * PP + p];
        float dy = vp[(3 * lab + 1) * PP + p];
        dz       = vp[(3 * lab + 2) * PP + p];
        float dn = sqrtf(dx * dx + dy * dy) + EPSF;
        ux = dx / dn;
        uy = dy / dn;
    }
    if (t < WW) {                               // count each pixel once
        unsigned m = __match_any_sync(0xffffffffu, lab);
        if (lane == __ffs(m) - 1) atomicAdd(&sCC[lab], __popc(m));
        // per-warp class membership masks (warps 0..9 only; copies identical)
        #pragma unroll
        for (int c = 0; c < NC; c++) {
            unsigned mm = __ballot_sync(0xffffffffu, lab == c);
            if (lane == c) sClsm[wid * NC + c] = mm;
        }
    }
    __syncthreads();

    // ---------------- vote: ballot per (warp, query), store raw mask ---------
    // copy 0 (warps 0..9): query rows 0..7; copy 1 (warps 10..19): rows 8..14.
    // FP sequence == ibit exactly -> identical vote bits.
    {
        int copy = wid >= NW;
        int ws   = copy ? (wid - NW) : wid;           // mask slot
        int r0   = copy ? 8 : 0;
        int r1   = copy ? QH : 8;
        float fpx = (float)px;
        unsigned int* __restrict__ mk = sB.masks;
        for (int r = r0; r < r1; r++) {
            float cy = (float)(r * QSKIP) - (float)row;   // exact small ints
            float K  = (0.81f * cy) * cy;
            float w  = fmaf(cy, uy, -C1F);
            float cx = -fpx;                              // qx = 0
            int qa = r * QW * NW + ws;
            #pragma unroll 5
            for (int i = 0; i < QW; i++) {
                float s   = cx * cx;
                float rhs = fmaf(s, 0.81f, K);
                float tv  = fmaf(cx, ux, w);
                float tt  = tv * fabsf(tv);
                float d   = fmaf(tt, -1.0f, rhs);
                unsigned bits = __ballot_sync(0xffffffffu,
                                              (int)__float_as_uint(d) < 0);
                if (lane == 0) mk[qa] = bits;             // single STS.32
                qa += NW;
                cx += 16.0f;                              // exact small ints
            }
        }
    }
    __syncthreads();

    // ---------------- merge: per-query popc against class masks --------------
    if (t < NQ) {
        unsigned cnt[NC];
        #pragma unroll
        for (int c = 0; c < NC; c++) cnt[c] = 0;
        #pragma unroll
        for (int w = 0; w < NW; w++) {
            unsigned m = sB.masks[t * NW + w];
            if (m) {
                const unsigned* cm = &sClsm[w * NC];      // broadcast LDS
                #pragma unroll
                for (int c = 1; c < NC; c++)
                    cnt[c] += __popc(m & cm[c]);
            }
        }
        // pack 4 u16 lanes per u64, 6 REDs per query (exact integer sums)
        #pragma unroll
        for (int g = 0; g < NR; g++) {
            int c0 = 4 * g;
            ull v = (ull)cnt[c0];
            if (c0 + 1 < NC) v |= (ull)cnt[c0 + 1] << 16;
            if (c0 + 2 < NC) v |= (ull)cnt[c0 + 2] << 32;
            if (c0 + 3 < NC) v |= (ull)cnt[c0 + 3] << 48;
            if (v) atomicAdd(&g_accP[t * NR + g], v);
        }
    }
    if (t < NC && sCC[t]) atomicAdd(&g_clsCnt[t], sCC[t]);

    // ---------------- grid barrier (2 blocks/SM => all 240 co-resident) ------
    __threadfence();
    __syncthreads();
    if (t == 0) {
        atomicAdd(&g_phase1, 1);
        while (atomicAdd(&g_phase1, 0) < BLKS) __nanosleep(64);
    }
    __syncthreads();

    // ---------------- phase 2: stage table (overwrites masks) ----------------
    for (int i = t; i < NQ * NR; i += THR) sB.tab[i] = __ldcg(&g_accP[i]);
    __syncthreads();

    // per-class argmax on u16 lanes, integer compare (first-index ties)
    {
        int w = t >> 5;                          // 20 warps
        for (int c = w; c < NC; c += 20) {
            int g  = c >> 2;
            int sh = (c & 3) * 16;
            int best = -1, bq = 0;
            for (int q = lane; q < NQ; q += 32) {
                int v = (int)((sB.tab[q * NR + g] >> sh) & 0xFFFFu);
                if (v > best) { best = v; bq = q; }
            }
            #pragma unroll
            for (int off = 16; off; off >>= 1) {
                int ov = __shfl_down_sync(0xffffffffu, best, off);
                int oq = __shfl_down_sync(0xffffffffu, bq,   off);
                if (ov > best || (ov == best && oq < bq)) { best = ov; bq = oq; }
            }
            if (lane == 0) { sBQ[c] = bq; sBV[c] = (float)best; }
        }
    }
    __syncthreads();

    // z-sum: each pixel once (t < 320); registers survived the barrier
    if (t < WW && lab > 0) {
        int q = sBQ[lab];
        float qx = (float)((q % QW) * QSKIP);
        float qy = (float)((q / QW) * QSKIP);
        float cy = qy - (float)row;
        float K  = (0.81f * cy) * cy;
        float cx = qx - (float)px;
        if (ibit(cx, cy, ux, uy, K))             // same rounding as vote
            atomicAdd(&sZ[lab], dz);
    }
    __syncthreads();
    if (t < NC && sZ[t] != 0.0f) atomicAdd(&g_zsum[t], sZ[t]);
    __threadfence();
    __syncthreads();
    if (t == 0) {
        if (atomicAdd(&g_phase2, 1) == BLKS - 1) sLast = 1;
    }
    __syncthreads();
    if (!sLast) return;

    // ================= last block: assemble output + reset scratch ===========
    if (t < NC) {
        int c = t;
        float fx  = mdata[0] + EPSF;
        float fy  = mdata[4] + EPSF;
        float ppx = mdata[2];
        float ppy = mdata[5];

        float bv = sBV[c];
        int   bq = sBQ[c];
        float bx = (float)((bq % QW) * QSKIP);
        float by = (float)((bq / QW) * QSKIP);

        float cc = (float)__ldcg(&g_clsCnt[c]);
        float z  = __ldcg(&g_zsum[c]) / (bv + EPSF);   // cnt == best_votes

        float ex = extents[c * 3 + 0];
        float ey = extents[c * 3 + 1];
        float ez = extents[c * 3 + 2];
        float half = 0.5f * sqrtf(ex * ex + ey * ey + ez * ez);

        float zsafe = (fabsf(z) > EPSF) ? z : EPSF;
        float r = fx * half / zsafe;

        bool valid = (bv >= 50.0f) && (cc >= 500.0f) && (bv / (cc + EPSF) >= 0.02f);
        float score = valid ? bv : 0.0f;

        float* o = out + c * 14;
        o[0]  = 0.0f;
        o[1]  = (float)c;
        o[2]  = bx - r;
        o[3]  = by - r;
        o[4]  = bx + r;
        o[5]  = by + r;
        o[6]  = score;
        o[7]  = poses[c * 13 + 6];
        o[8]  = poses[c * 13 + 7];
        o[9]  = poses[c * 13 + 8];
        o[10] = poses[c * 13 + 9];
        o[11] = (bx - ppx) * z / fx;
        o[12] = (by - ppy) * z / fy;
        o[13] = z;

        g_clsCnt[c] = 0;                 // reset for next graph replay
        g_zsum[c]   = 0.0f;
    }
    for (int i = t; i < NQ * NR; i += THR) g_accP[i] = 0ULL;
    __threadfence();
    if (t == 0) { g_phase1 = 0; g_phase2 = 0; }
}

// ---------------- launch ------------------------------------------------------
extern "C" void kernel_launch(void* const* d_in, const int* in_sizes, int n_in,
                              void* d_out, int out_size) {
    const int*   label   = (const int*)  d_in[0];   // (1,240,320) int32
    const float* vp      = (const float*)d_in[1];   // (1,66,240,320) f32
    const float* extents = (const float*)d_in[2];   // (22,3) f32
    const float* poses   = (const float*)d_in[3];   // (22,13) f32
    const float* mdata   = (const float*)d_in[4];   // (1,9) f32
    float*       out     = (float*)d_out;           // (1,22,14) f32

    k_all<<<BLKS, THR>>>(label, vp, extents, poses, mdata, out);
}

// round 15
// speedup vs baseline: 2.0728x; 1.0656x over previous
#include <cuda_runtime.h>
#include <cuda_bf16.h>

#define PP     76800     // H*W
#define HH     240
#define WW     320
#define NC     22        // classes
#define NR     6         // u64 groups of 4 u16 class lanes
#define NQ     300       // query points (15*20)
#define QW     20
#define QH     15
#define QSKIP  16
#define EPSF   1e-6f
#define C1F    (0.9f * 1e-6f)

#define THR    640       // 2 image rows of pixels per block
#define NW     20        // pixel warps per block (mask slots)
#define NWP    21        // padded mask row stride (gcd(21,32)=1)
#define BLKS   120       // < 148 SMs => co-resident at ANY occupancy

typedef unsigned long long ull;

// ---------------- device scratch (zero-init; reset by last block each launch) -
__device__ ull   g_accP[NQ * NR];
__device__ int   g_clsCnt[NC];
__device__ float g_zsum[NC];
__device__ int   g_phase1;
__device__ int   g_phase2;

// Exact inlier bit — byte-identical op sequence to rounds 4..14.
__device__ __forceinline__ unsigned ibit(float cx, float cy, float ux, float uy,
                                         float K) {
    float s   = cx * cx;
    float rhs = fmaf(s, 0.81f, K);
    float w   = fmaf(cy, uy, -C1F);
    float tv  = fmaf(cx, ux, w);
    float tt  = tv * fabsf(tv);
    float d   = fmaf(tt, -1.0f, rhs);
    return __float_as_uint(d) >> 31;
}

// =============== single persistent kernel ====================================
__global__ void __launch_bounds__(THR) k_all(const int* __restrict__ label,
                                             const float* __restrict__ vp,
                                             const float* __restrict__ extents,
                                             const float* __restrict__ poses,
                                             const float* __restrict__ mdata,
                                             float* __restrict__ out) {
    __shared__ union {
        unsigned int masks[NQ * NWP];  // 25.2 KB inlier masks [q][pixel-warp]
        ull          tab[NQ * NR];     // 14.4 KB staged vote table (phase 2)
    } sB;
    __shared__ unsigned int sClsm[NW * NC];   // per-pixel-warp class masks
    __shared__ int   sCC[NC];
    __shared__ int   sBQ[NC];
    __shared__ float sBV[NC];
    __shared__ float sZ[NC];
    __shared__ int   sLast;

    int t    = threadIdx.x;
    int lane = t & 31;
    int wid  = t >> 5;
    int blk  = blockIdx.x;

    if (t < NC) { sCC[t] = 0; sZ[t] = 0.0f; }
    if (t == 0) sLast = 0;

    // ---------------- prep: one pixel per thread (2 rows = 640 px) -----------
    int sub = (t >= WW);                        // row within block
    int col = t - sub * WW;                     // pixel column
    int p   = blk * (2 * WW) + t;
    int lab = label[p];
    float ux = 0.0f, uy = 0.0f, dz = 0.0f;
    if (lab > 0) {
        float dx = vp[(3 * lab + 0) * PP + p];
        float dy = vp[(3 * lab + 1) * PP + p];
        dz       = vp[(3 * lab + 2) * PP + p];
        float dn = sqrtf(dx * dx + dy * dy) + EPSF;
        ux = dx / dn;
        uy = dy / dn;
    }
    {
        unsigned m = __match_any_sync(0xffffffffu, lab);
        if (lane == __ffs(m) - 1) atomicAdd(&sCC[lab], __popc(m));
    }
    // per-warp class membership masks
    #pragma unroll
    for (int c = 0; c < NC; c++) {
        unsigned mm = __ballot_sync(0xffffffffu, lab == c);
        if (lane == c) sClsm[wid * NC + c] = mm;
    }
    __syncthreads();

    // ---------------- vote: register bit-accumulate + warp bit-transpose -----
    // Per lane: 32 query bits built with full-rate ALU (no VOTE in hot loop).
    // 5-step shfl-xor 32x32 bit transpose => lane=query, bit=pixel (== ballot
    // layout). FP sequence == ibit exactly -> identical vote bits.
    {
        float fpx  = (float)col;
        float frow = (float)(blk * 2 + sub);
        unsigned int* __restrict__ mk = sB.masks;
        #pragma unroll
        for (int g = 0; g < 10; g++) {
            unsigned bits = 0;
            #pragma unroll
            for (int k = 0; k < 32; k++) {
                const int q = g * 32 + k;
                if (q < NQ) {
                    const int r = q / QW;
                    const int i = q - r * QW;
                    float cy  = (float)(r * QSKIP) - frow;   // exact small ints
                    float K   = (0.81f * cy) * cy;           // CSE'd per row
                    float w   = fmaf(cy, uy, -C1F);          // CSE'd per row
                    float cx  = (float)(i * QSKIP) - fpx;    // exact small ints
                    float s   = cx * cx;
                    float rhs = fmaf(s, 0.81f, K);
                    float tv  = fmaf(cx, ux, w);
                    float tt  = tv * fabsf(tv);
                    float d   = fmaf(tt, -1.0f, rhs);
                    bits |= ((__float_as_uint(d) >> 31) << k);
                }
            }
            // 32x32 bit-matrix transpose across the warp (block-swap network)
            unsigned x = bits, pr;
            pr = __shfl_xor_sync(0xffffffffu, x, 16);
            x = (lane & 16) ? ((x & 0xFFFF0000u) | ((pr & 0xFFFF0000u) >> 16))
                            : ((x & 0x0000FFFFu) | ((pr & 0x0000FFFFu) << 16));
            pr = __shfl_xor_sync(0xffffffffu, x, 8);
            x = (lane & 8)  ? ((x & 0xFF00FF00u) | ((pr & 0xFF00FF00u) >> 8))
                            : ((x & 0x00FF00FFu) | ((pr & 0x00FF00FFu) << 8));
            pr = __shfl_xor_sync(0xffffffffu, x, 4);
            x = (lane & 4)  ? ((x & 0xF0F0F0F0u) | ((pr & 0xF0F0F0F0u) >> 4))
                            : ((x & 0x0F0F0F0Fu) | ((pr & 0x0F0F0F0Fu) << 4));
            pr = __shfl_xor_sync(0xffffffffu, x, 2);
            x = (lane & 2)  ? ((x & 0xCCCCCCCCu) | ((pr & 0xCCCCCCCCu) >> 2))
                            : ((x & 0x33333333u) | ((pr & 0x33333333u) << 2));
            pr = __shfl_xor_sync(0xffffffffu, x, 1);
            x = (lane & 1)  ? ((x & 0xAAAAAAAAu) | ((pr & 0xAAAAAAAAu) >> 1))
                            : ((x & 0x55555555u) | ((pr & 0x55555555u) << 1));
            int q = g * 32 + lane;
            if (q < NQ) mk[q * NWP + wid] = x;   // conflict-free (stride 21)
        }
    }
    __syncthreads();

    // ---------------- merge: per-query popc against class masks --------------
    if (t < NQ) {
        unsigned cnt[NC];
        #pragma unroll
        for (int c = 0; c < NC; c++) cnt[c] = 0;
        #pragma unroll
        for (int w = 0; w < NW; w++) {
            unsigned m = sB.masks[t * NWP + w];
            if (m) {
                const unsigned* cm = &sClsm[w * NC];      // broadcast LDS
                #pragma unroll
                for (int c = 1; c < NC; c++)
                    cnt[c] += __popc(m & cm[c]);
            }
        }
        // pack 4 u16 lanes per u64, 6 REDs per query (exact integer sums)
        #pragma unroll
        for (int g = 0; g < NR; g++) {
            int c0 = 4 * g;
            ull v = (ull)cnt[c0];
            if (c0 + 1 < NC) v |= (ull)cnt[c0 + 1] << 16;
            if (c0 + 2 < NC) v |= (ull)cnt[c0 + 2] << 32;
            if (c0 + 3 < NC) v |= (ull)cnt[c0 + 3] << 48;
            if (v) atomicAdd(&g_accP[t * NR + g], v);
        }
    }
    if (t < NC && sCC[t]) atomicAdd(&g_clsCnt[t], sCC[t]);

    // ---------------- grid barrier (120 blocks <= 148 SMs: deadlock-safe) ----
    __threadfence();
    __syncthreads();
    if (t == 0) {
        atomicAdd(&g_phase1, 1);
        while (atomicAdd(&g_phase1, 0) < BLKS) __nanosleep(64);
    }
    __syncthreads();

    // ---------------- phase 2: stage table (overwrites masks) ----------------
    for (int i = t; i < NQ * NR; i += THR) sB.tab[i] = __ldcg(&g_accP[i]);
    __syncthreads();

    // per-class argmax on u16 lanes, integer compare (first-index ties)
    {
        int w = t >> 5;                          // 20 warps
        for (int c = w; c < NC; c += NW) {
            int g  = c >> 2;
            int sh = (c & 3) * 16;
            int best = -1, bq = 0;
            for (int q = lane; q < NQ; q += 32) {
                int v = (int)((sB.tab[q * NR + g] >> sh) & 0xFFFFu);
                if (v > best) { best = v; bq = q; }
            }
            #pragma unroll
            for (int off = 16; off; off >>= 1) {
                int ov = __shfl_down_sync(0xffffffffu, best, off);
                int oq = __shfl_down_sync(0xffffffffu, bq,   off);
                if (ov > best || (ov == best && oq < bq)) { best = ov; bq = oq; }
            }
            if (lane == 0) { sBQ[c] = bq; sBV[c] = (float)best; }
        }
    }
    __syncthreads();

    // z-sum: this thread's pixel (registers survived the barrier)
    if (lab > 0) {
        int q = sBQ[lab];
        float qx = (float)((q % QW) * QSKIP);
        float qy = (float)((q / QW) * QSKIP);
        float cy = qy - (float)(blk * 2 + sub);
        float K  = (0.81f * cy) * cy;
        float cx = qx - (float)col;
        if (ibit(cx, cy, ux, uy, K))             // same rounding as vote
            atomicAdd(&sZ[lab], dz);
    }
    __syncthreads();
    if (t < NC && sZ[t] != 0.0f) atomicAdd(&g_zsum[t], sZ[t]);
    __threadfence();
    __syncthreads();
    if (t == 0) {
        if (atomicAdd(&g_phase2, 1) == BLKS - 1) sLast = 1;
    }
    __syncthreads();
    if (!sLast) return;

    // ================= last block: assemble output + reset scratch ===========
    if (t < NC) {
        int c = t;
        float fx  = mdata[0] + EPSF;
        float fy  = mdata[4] + EPSF;
        float ppx = mdata[2];
        float ppy = mdata[5];

        float bv = sBV[c];
        int   bq = sBQ[c];
        float bx = (float)((bq % QW) * QSKIP);
        float by = (float)((bq / QW) * QSKIP);

        float cc = (float)__ldcg(&g_clsCnt[c]);
        float z  = __ldcg(&g_zsum[c]) / (bv + EPSF);   // cnt == best_votes

        float ex = extents[c * 3 + 0];
        float ey = extents[c * 3 + 1];
        float ez = extents[c * 3 + 2];
        float half = 0.5f * sqrtf(ex * ex + ey * ey + ez * ez);

        float zsafe = (fabsf(z) > EPSF) ? z : EPSF;
        float r = fx * half / zsafe;

        bool valid = (bv >= 50.0f) && (cc >= 500.0f) && (bv / (cc + EPSF) >= 0.02f);
        float score = valid ? bv : 0.0f;

        float* o = out + c * 14;
        o[0]  = 0.0f;
        o[1]  = (float)c;
        o[2]  = bx - r;
        o[3]  = by - r;
        o[4]  = bx + r;
        o[5]  = by + r;
        o[6]  = score;
        o[7]  = poses[c * 13 + 6];
        o[8]  = poses[c * 13 + 7];
        o[9]  = poses[c * 13 + 8];
        o[10] = poses[c * 13 + 9];
        o[11] = (bx - ppx) * z / fx;
        o[12] = (by - ppy) * z / fy;
        o[13] = z;

        g_clsCnt[c] = 0;                 // reset for next graph replay
        g_zsum[c]   = 0.0f;
    }
    for (int i = t; i < NQ * NR; i += THR) g_accP[i] = 0ULL;
    __threadfence();
    if (t == 0) { g_phase1 = 0; g_phase2 = 0; }
}

// ---------------- launch ------------------------------------------------------
extern "C" void kernel_launch(void* const* d_in, const int* in_sizes, int n_in,
                              void* d_out, int out_size) {
    const int*   label   = (const int*)  d_in[0];   // (1,240,320) int32
    const float* vp      = (const float*)d_in[1];   // (1,66,240,320) f32
    const float* extents = (const float*)d_in[2];   // (22,3) f32
    const float* poses   = (const float*)d_in[3];   // (22,13) f32
    const float* mdata   = (const float*)d_in[4];   // (1,9) f32
    float*       out     = (float*)d_out;           // (1,22,14) f32

    k_all<<<BLKS, THR>>>(label, vp, extents, poses, mdata, out);
}